// round 1
// baseline (speedup 1.0000x reference)
#include <cuda_runtime.h>
#include <math.h>

#define S 2048
#define D 2048
#define H 32
#define KVH 8
#define HD 64
#define NREP (H / KVH)

// Scratch (device globals -- no allocation allowed)
__device__ float g_Q[S * H * HD];    // 16 MB
__device__ float g_K[S * KVH * HD];  // 4 MB
__device__ float g_V[S * KVH * HD];  // 4 MB
__device__ float g_O[S * H * HD];    // 16 MB

// ---------------------------------------------------------------------------
// Classic register-blocked SGEMM: C[M,N] = A[M,K] @ B[K,N], row-major fp32.
// 128x128 block tile, BK=16, 256 threads, 8x8 per thread.
// ---------------------------------------------------------------------------
#define BM 128
#define BN 128
#define BKK 16

__global__ __launch_bounds__(256) void sgemm_kernel(
    const float* __restrict__ A, const float* __restrict__ B,
    float* __restrict__ C, int M, int N, int K) {
  __shared__ float As[BKK][BM];  // A tile, transposed (k-major)
  __shared__ float Bs[BKK][BN];

  const int bx = blockIdx.x, by = blockIdx.y;
  const int tid = threadIdx.x;
  const int tx = tid % 16;  // 16 col-groups of 8
  const int ty = tid / 16;  // 16 row-groups of 8

  const float* Ablk = A + (size_t)by * BM * K;
  const float* Bblk = B + (size_t)bx * BN;

  float acc[8][8];
#pragma unroll
  for (int i = 0; i < 8; i++)
#pragma unroll
    for (int j = 0; j < 8; j++) acc[i][j] = 0.0f;

  for (int k0 = 0; k0 < K; k0 += BKK) {
    // Load A tile (128x16): 512 float4 vectors, 2 per thread. Transpose to As.
#pragma unroll
    for (int i = 0; i < 2; i++) {
      int v = tid + i * 256;
      int r = v >> 2;              // row 0..127
      int c4 = (v & 3) * 4;        // col 0,4,8,12
      float4 f = *(const float4*)(Ablk + (size_t)r * K + k0 + c4);
      As[c4 + 0][r] = f.x;
      As[c4 + 1][r] = f.y;
      As[c4 + 2][r] = f.z;
      As[c4 + 3][r] = f.w;
    }
    // Load B tile (16x128): 512 float4 vectors, 2 per thread.
#pragma unroll
    for (int i = 0; i < 2; i++) {
      int v = tid + i * 256;
      int r = v >> 5;              // row 0..15
      int c = (v & 31) * 4;        // col 0..124
      *(float4*)&Bs[r][c] = *(const float4*)(Bblk + (size_t)(k0 + r) * N + c);
    }
    __syncthreads();

#pragma unroll
    for (int k = 0; k < BKK; k++) {
      float a[8], b[8];
      const float4* ap = (const float4*)&As[k][ty * 8];
      const float4* bp = (const float4*)&Bs[k][tx * 8];
      float4 a0 = ap[0], a1 = ap[1];
      float4 b0 = bp[0], b1 = bp[1];
      a[0] = a0.x; a[1] = a0.y; a[2] = a0.z; a[3] = a0.w;
      a[4] = a1.x; a[5] = a1.y; a[6] = a1.z; a[7] = a1.w;
      b[0] = b0.x; b[1] = b0.y; b[2] = b0.z; b[3] = b0.w;
      b[4] = b1.x; b[5] = b1.y; b[6] = b1.z; b[7] = b1.w;
#pragma unroll
      for (int i = 0; i < 8; i++)
#pragma unroll
        for (int j = 0; j < 8; j++) acc[i][j] += a[i] * b[j];
    }
    __syncthreads();
  }

  float* Cblk = C + (size_t)by * BM * N + bx * BN;
#pragma unroll
  for (int i = 0; i < 8; i++) {
#pragma unroll
    for (int j = 0; j < 8; j += 4) {
      *(float4*)&Cblk[(size_t)(ty * 8 + i) * N + tx * 8 + j] =
          make_float4(acc[i][j], acc[i][j + 1], acc[i][j + 2], acc[i][j + 3]);
    }
  }
}

// ---------------------------------------------------------------------------
// RoPE (interleaved pairs), matches reference fp32 math.
// X: [S][nheads*HD]. One thread per (s, h, pair).
// ---------------------------------------------------------------------------
__global__ void rope_kernel(float* __restrict__ X, int nheads, int total) {
  int idx = blockIdx.x * blockDim.x + threadIdx.x;
  if (idx >= total) return;
  int i = idx % (HD / 2);
  int tmp = idx / (HD / 2);
  int h = tmp % nheads;
  int s = tmp / nheads;
  float inv = 1.0f / powf(10000.0f, (2.0f * i) / (float)HD);
  float ang = (float)s * inv;
  float c = cosf(ang);
  float sn = sinf(ang);
  float* p = X + (size_t)s * nheads * HD + h * HD + 2 * i;
  float xr = p[0], xi = p[1];
  p[0] = xr * c - xi * sn;
  p[1] = xr * sn + xi * c;
}

// ---------------------------------------------------------------------------
// Flash-attention style causal attention, fp32, online softmax.
// Block: one (head, q-tile of 64). 256 threads; 4x4 micro-tile per thread.
// Dynamic smem: Qs[HD][BQ] + Ks[HD][BKV] + Vs[BKV][HD] + Ps[BKV][BQ] = 64 KB.
// ---------------------------------------------------------------------------
#define BQ 64
#define BKV 64

__global__ __launch_bounds__(256) void attn_kernel(
    const float* __restrict__ Q, const float* __restrict__ K,
    const float* __restrict__ V, float* __restrict__ O) {
  extern __shared__ float sm[];
  float* Qs = sm;                  // [HD][BQ]   d-major
  float* Ks = Qs + HD * BQ;        // [HD][BKV]  d-major
  float* Vs = Ks + HD * BKV;       // [BKV][HD]  k-major
  float* Ps = Vs + BKV * HD;       // [BKV][BQ]  k-major (P transposed)

  const int h = blockIdx.x;    // 0..H-1
  const int qt = blockIdx.y;   // 0..S/BQ-1
  const int kvh = h / NREP;
  const int q0 = qt * BQ;
  const int tid = threadIdx.x;
  const int tx = tid % 16;  // key/dim col-group (4 wide)
  const int ty = tid / 16;  // query row-group (4 wide)

  // Load Q tile: Q[q0+q][h*HD+d] -> Qs[d][q]
  for (int v = tid; v < BQ * (HD / 4); v += 256) {
    int q = v / (HD / 4);
    int d4 = (v % (HD / 4)) * 4;
    float4 f = *(const float4*)(Q + (size_t)(q0 + q) * (H * HD) + h * HD + d4);
    Qs[(d4 + 0) * BQ + q] = f.x;
    Qs[(d4 + 1) * BQ + q] = f.y;
    Qs[(d4 + 2) * BQ + q] = f.z;
    Qs[(d4 + 3) * BQ + q] = f.w;
  }

  float m_i[4], l_i[4], acc[4][4];
#pragma unroll
  for (int i = 0; i < 4; i++) {
    m_i[i] = -1e30f;
    l_i[i] = 0.0f;
#pragma unroll
    for (int j = 0; j < 4; j++) acc[i][j] = 0.0f;
  }

  const int kend = q0 + BQ;  // causal: keys < kend
  for (int k0 = 0; k0 < kend; k0 += BKV) {
    __syncthreads();  // Qs ready (1st iter); Vs/Ps reads from prev iter done

    // Load K tile -> Ks[d][k] (transposed), V tile -> Vs[k][d]
    for (int v = tid; v < BKV * (HD / 4); v += 256) {
      int kk = v / (HD / 4);
      int d4 = (v % (HD / 4)) * 4;
      float4 f = *(const float4*)(K + (size_t)(k0 + kk) * (KVH * HD) + kvh * HD + d4);
      Ks[(d4 + 0) * BKV + kk] = f.x;
      Ks[(d4 + 1) * BKV + kk] = f.y;
      Ks[(d4 + 2) * BKV + kk] = f.z;
      Ks[(d4 + 3) * BKV + kk] = f.w;
      *(float4*)&Vs[kk * HD + d4] =
          *(const float4*)(V + (size_t)(k0 + kk) * (KVH * HD) + kvh * HD + d4);
    }
    __syncthreads();

    // Scores: 4x4 per thread. q rows = ty*4.., k cols = tx*4..
    float sc[4][4];
#pragma unroll
    for (int i = 0; i < 4; i++)
#pragma unroll
      for (int j = 0; j < 4; j++) sc[i][j] = 0.0f;

#pragma unroll 8
    for (int d = 0; d < HD; d++) {
      float4 av = *(const float4*)&Qs[d * BQ + ty * 4];
      float4 bv = *(const float4*)&Ks[d * BKV + tx * 4];
      float a[4] = {av.x, av.y, av.z, av.w};
      float b[4] = {bv.x, bv.y, bv.z, bv.w};
#pragma unroll
      for (int i = 0; i < 4; i++)
#pragma unroll
        for (int j = 0; j < 4; j++) sc[i][j] += a[i] * b[j];
    }

    const float scale = 0.125f;  // 1/sqrt(64)
#pragma unroll
    for (int i = 0; i < 4; i++) {
#pragma unroll
      for (int j = 0; j < 4; j++) {
        int gq = q0 + ty * 4 + i;
        int gk = k0 + tx * 4 + j;
        sc[i][j] = (gk <= gq) ? sc[i][j] * scale : -1e30f;
      }
    }

    // Online softmax. Row owned by 16 contiguous lanes (same ty).
#pragma unroll
    for (int i = 0; i < 4; i++) {
      float mx = fmaxf(fmaxf(sc[i][0], sc[i][1]), fmaxf(sc[i][2], sc[i][3]));
#pragma unroll
      for (int off = 8; off >= 1; off >>= 1)
        mx = fmaxf(mx, __shfl_xor_sync(0xffffffffu, mx, off, 16));
      float m_new = fmaxf(m_i[i], mx);
      float corr = __expf(m_i[i] - m_new);
      m_i[i] = m_new;
      l_i[i] *= corr;
#pragma unroll
      for (int j = 0; j < 4; j++) acc[i][j] *= corr;
      float ps = 0.0f;
#pragma unroll
      for (int j = 0; j < 4; j++) {
        float p = __expf(sc[i][j] - m_new);
        sc[i][j] = p;
        ps += p;
      }
#pragma unroll
      for (int off = 8; off >= 1; off >>= 1)
        ps += __shfl_xor_sync(0xffffffffu, ps, off, 16);
      l_i[i] += ps;
    }

    // Write P transposed: Ps[k][q]
#pragma unroll
    for (int i = 0; i < 4; i++)
#pragma unroll
      for (int j = 0; j < 4; j++)
        Ps[(tx * 4 + j) * BQ + (ty * 4 + i)] = sc[i][j];
    __syncthreads();

    // acc[4q][4d] += P @ V ; d cols = tx*4..
#pragma unroll 8
    for (int k = 0; k < BKV; k++) {
      float4 pv = *(const float4*)&Ps[k * BQ + ty * 4];
      float4 vv = *(const float4*)&Vs[k * HD + tx * 4];
      float pa[4] = {pv.x, pv.y, pv.z, pv.w};
      float vb[4] = {vv.x, vv.y, vv.z, vv.w};
#pragma unroll
      for (int i = 0; i < 4; i++)
#pragma unroll
        for (int j = 0; j < 4; j++) acc[i][j] += pa[i] * vb[j];
    }
  }

  // Epilogue: normalize and write O[q][h*HD+d]
#pragma unroll
  for (int i = 0; i < 4; i++) {
    float inv_l = 1.0f / l_i[i];
    int gq = q0 + ty * 4 + i;
#pragma unroll
    for (int j = 0; j < 4; j++)
      O[(size_t)gq * (H * HD) + h * HD + tx * 4 + j] = acc[i][j] * inv_l;
  }
}

// ---------------------------------------------------------------------------
// Launch
// ---------------------------------------------------------------------------
extern "C" void kernel_launch(void* const* d_in, const int* in_sizes, int n_in,
                              void* d_out, int out_size) {
  const float* hs = (const float*)d_in[0];  // [1,2048,2048]
  const float* Wq = (const float*)d_in[1];  // [2048, 2048]
  const float* Wk = (const float*)d_in[2];  // [2048, 512]
  const float* Wv = (const float*)d_in[3];  // [2048, 512]
  const float* Wo = (const float*)d_in[4];  // [2048, 2048]
  float* out = (float*)d_out;               // [1,2048,2048]

  float *Qp, *Kp, *Vp, *Op;
  cudaGetSymbolAddress((void**)&Qp, g_Q);
  cudaGetSymbolAddress((void**)&Kp, g_K);
  cudaGetSymbolAddress((void**)&Vp, g_V);
  cudaGetSymbolAddress((void**)&Op, g_O);

  // QKV projections
  {
    dim3 blk(256);
    dim3 gq(H * HD / BN, S / BM);    // 16 x 16
    dim3 gkv(KVH * HD / BN, S / BM); // 4 x 16
    sgemm_kernel<<<gq, blk>>>(hs, Wq, Qp, S, H * HD, D);
    sgemm_kernel<<<gkv, blk>>>(hs, Wk, Kp, S, KVH * HD, D);
    sgemm_kernel<<<gkv, blk>>>(hs, Wv, Vp, S, KVH * HD, D);
  }

  // RoPE on Q and K
  {
    int totq = S * H * (HD / 2);
    int totk = S * KVH * (HD / 2);
    rope_kernel<<<(totq + 255) / 256, 256>>>(Qp, H, totq);
    rope_kernel<<<(totk + 255) / 256, 256>>>(Kp, KVH, totk);
  }

  // Attention
  {
    static int smem_set = 0;
    int smem_bytes = (HD * BQ + HD * BKV + BKV * HD + BKV * BQ) * sizeof(float);  // 64 KB
    cudaFuncSetAttribute(attn_kernel, cudaFuncAttributeMaxDynamicSharedMemorySize,
                         smem_bytes);
    (void)smem_set;
    dim3 grid(H, S / BQ);  // 32 x 32
    attn_kernel<<<grid, 256, smem_bytes>>>(Qp, Kp, Vp, Op);
  }

  // Output projection
  {
    dim3 blk(256);
    dim3 g(D / BN, S / BM);  // 16 x 16
    sgemm_kernel<<<g, blk>>>(Op, Wo, out, S, D, H * HD);
  }
}

// round 3
// speedup vs baseline: 1.7991x; 1.7991x over previous
#include <cuda_runtime.h>
#include <cuda_bf16.h>
#include <cstdint>
#include <math.h>

#define S 2048
#define D 2048
#define H 32
#define KVH 8
#define HD 64
#define NREP (H / KVH)
#define QKV_N 3072  // 2048 Q + 512 K + 512 V
#define KCOL 2048
#define VCOL 2560

// ---------------------------------------------------------------------------
// Device-global scratch (no allocations allowed)
// ---------------------------------------------------------------------------
__device__ float g_QKV[S * QKV_N];                                    // 24 MB
__device__ __nv_bfloat16 g_Xhi[S * D], g_Xlo[S * D];                  // 16 MB
__device__ __nv_bfloat16 g_Ohi[S * D], g_Olo[S * D];                  // 16 MB
__device__ __nv_bfloat16 g_WqkvThi[QKV_N * D], g_WqkvTlo[QKV_N * D];  // 24 MB
__device__ __nv_bfloat16 g_WoThi[D * D], g_WoTlo[D * D];              // 16 MB

// ---------------------------------------------------------------------------
// Portable tensor-core helpers (sm_80+ ISA: mma.sync / ldmatrix / cp.async)
// ---------------------------------------------------------------------------
__device__ __forceinline__ uint32_t smem_u32(const void* p) {
  uint32_t a;
  asm("{ .reg .u64 t; cvta.to.shared.u64 t, %1; cvt.u32.u64 %0, t; }"
      : "=r"(a) : "l"(p));
  return a;
}

__device__ __forceinline__ void ldsm_x4(uint32_t* r, uint32_t addr) {
  asm volatile(
      "ldmatrix.sync.aligned.m8n8.x4.shared.b16 {%0,%1,%2,%3}, [%4];"
      : "=r"(r[0]), "=r"(r[1]), "=r"(r[2]), "=r"(r[3])
      : "r"(addr));
}

__device__ __forceinline__ void mma16816(float* d, const uint32_t* a,
                                         const uint32_t* b) {
  asm volatile(
      "mma.sync.aligned.m16n8k16.row.col.f32.bf16.bf16.f32 "
      "{%0,%1,%2,%3}, {%4,%5,%6,%7}, {%8,%9}, {%0,%1,%2,%3};"
      : "+f"(d[0]), "+f"(d[1]), "+f"(d[2]), "+f"(d[3])
      : "r"(a[0]), "r"(a[1]), "r"(a[2]), "r"(a[3]), "r"(b[0]), "r"(b[1]));
}

__device__ __forceinline__ void cp_async16(uint32_t saddr, const void* gptr) {
  asm volatile("cp.async.cg.shared.global [%0], [%1], 16;" ::
                   "r"(saddr), "l"(__cvta_generic_to_global(gptr)));
}
#define CP_COMMIT() asm volatile("cp.async.commit_group;" ::: "memory")
#define CP_WAIT0() asm volatile("cp.async.wait_group 0;" ::: "memory")

// ---------------------------------------------------------------------------
// Split fp32 -> bf16 hi/lo
// ---------------------------------------------------------------------------
__device__ __forceinline__ void split2(float x, __nv_bfloat16& h, __nv_bfloat16& l) {
  h = __float2bfloat16(x);
  l = __float2bfloat16(x - __bfloat162float(h));
}

__global__ void split_kernel(const float* __restrict__ in,
                             __nv_bfloat16* __restrict__ hi,
                             __nv_bfloat16* __restrict__ lo, int n4) {
  int i = blockIdx.x * blockDim.x + threadIdx.x;
  if (i >= n4) return;
  float4 v = ((const float4*)in)[i];
  __nv_bfloat16 h0, l0, h1, l1, h2, l2, h3, l3;
  split2(v.x, h0, l0); split2(v.y, h1, l1);
  split2(v.z, h2, l2); split2(v.w, h3, l3);
  __nv_bfloat162* hp = (__nv_bfloat162*)hi;
  __nv_bfloat162* lp = (__nv_bfloat162*)lo;
  hp[i * 2 + 0] = __halves2bfloat162(h0, h1);
  hp[i * 2 + 1] = __halves2bfloat162(h2, h3);
  lp[i * 2 + 0] = __halves2bfloat162(l0, l1);
  lp[i * 2 + 1] = __halves2bfloat162(l2, l3);
}

// Transpose W[K][N] fp32 -> T_hi/lo[N][K] bf16 (dst row stride = K)
__global__ void transpose_split_kernel(const float* __restrict__ W,
                                       __nv_bfloat16* __restrict__ Thi,
                                       __nv_bfloat16* __restrict__ Tlo,
                                       int N, int K) {
  __shared__ float t[32][33];
  int n0 = blockIdx.x * 32, k0 = blockIdx.y * 32;
  int tx = threadIdx.x, ty = threadIdx.y;  // (32, 8)
#pragma unroll
  for (int i = 0; i < 4; i++)
    t[ty + i * 8][tx] = W[(size_t)(k0 + ty + i * 8) * N + n0 + tx];
  __syncthreads();
#pragma unroll
  for (int i = 0; i < 4; i++) {
    int n = ty + i * 8;
    float x = t[tx][n];
    __nv_bfloat16 h, l;
    split2(x, h, l);
    size_t o = (size_t)(n0 + n) * K + k0 + tx;
    Thi[o] = h;
    Tlo[o] = l;
  }
}

// ---------------------------------------------------------------------------
// bf16x3-split GEMM on mma.sync: C[M,N] = A[M,K] @ B[K,N] (fp32-equivalent)
// A hi/lo bf16 [M][K]; B hi/lo bf16 TRANSPOSED [N][K] (both K-contiguous).
// Block 128x128, BK=32, 8 warps (warp tile 32x64), cp.async double buffer.
// ---------------------------------------------------------------------------
#define GBM 128
#define GBN 128
#define GKC 32
#define RS 40                  // smem row stride in bf16 elems (padding: no bank conflicts)
#define TILE_B (128 * RS * 2)  // 10240 bytes per operand tile
#define STAGE_B (4 * TILE_B)   // Ahi, Alo, Bhi, Blo
#define GEMM_SMEM (2 * STAGE_B)

__global__ __launch_bounds__(256) void gemm_bf16x3_kernel(
    const __nv_bfloat16* __restrict__ Ahi, const __nv_bfloat16* __restrict__ Alo,
    const __nv_bfloat16* __restrict__ Bhi, const __nv_bfloat16* __restrict__ Blo,
    float* __restrict__ C, int M, int N, int K) {
  extern __shared__ char smem[];
  const uint32_t sbase = smem_u32(smem);
  const int tid = threadIdx.x;
  const int wid = tid >> 5;
  const int lane = tid & 31;
  const int m0 = blockIdx.y * GBM;
  const int n0 = blockIdx.x * GBN;
  const int NC = K / GKC;

  const int wm = (wid & 3) * 32;   // warp m offset (4 warps)
  const int wn = (wid >> 2) * 64;  // warp n offset (2 warps)

  // ldmatrix lane addressing
  const int lrow = lane & 7;
  const int ltile = lane >> 3;
  // A tiles: m += (ltile&1)*8, k += (ltile>>1)*8
  const int a_r = (ltile & 1) * 8 + lrow;
  const int a_c = (ltile >> 1) * 8;
  // B tiles: n += (ltile>>1)*8, k += (ltile&1)*8
  const int b_r = (ltile >> 1) * 8 + lrow;
  const int b_c = (ltile & 1) * 8;

  const __nv_bfloat16* gA[2] = {Ahi + (size_t)m0 * K, Alo + (size_t)m0 * K};
  const __nv_bfloat16* gB[2] = {Bhi + (size_t)n0 * K, Blo + (size_t)n0 * K};

  auto load_stage = [&](int stg, int chunk) {
    const int kc = chunk * GKC;
    uint32_t sb = sbase + stg * STAGE_B;
#pragma unroll
    for (int t = 0; t < 4; t++) {
      const __nv_bfloat16* gp = (t < 2) ? gA[t] : gB[t - 2];
#pragma unroll
      for (int i = 0; i < 2; i++) {
        int v = tid + i * 256;       // 0..511
        int r = v >> 2;              // row 0..127
        int c = (v & 3) * 8;         // col 0,8,16,24 (elems)
        cp_async16(sb + t * TILE_B + (uint32_t)(r * RS + c) * 2,
                   gp + (size_t)r * K + kc + c);
      }
    }
    CP_COMMIT();
  };

  float acc[2][8][4];
#pragma unroll
  for (int f = 0; f < 2; f++)
#pragma unroll
    for (int g = 0; g < 8; g++)
#pragma unroll
      for (int x = 0; x < 4; x++) acc[f][g][x] = 0.0f;

  load_stage(0, 0);

  for (int c = 0; c < NC; c++) {
    CP_WAIT0();
    __syncthreads();
    if (c + 1 < NC) load_stage((c + 1) & 1, c + 1);

    uint32_t sb = sbase + (c & 1) * STAGE_B;
#pragma unroll
    for (int kk = 0; kk < 2; kk++) {
      const int k0 = kk * 16;
      uint32_t ah[2][4], al[2][4], bh[8][2], bl[8][2];
#pragma unroll
      for (int f = 0; f < 2; f++) {
        uint32_t ar = (uint32_t)((wm + f * 16 + a_r) * RS + k0 + a_c) * 2;
        ldsm_x4(ah[f], sb + 0 * TILE_B + ar);
        ldsm_x4(al[f], sb + 1 * TILE_B + ar);
      }
#pragma unroll
      for (int g2 = 0; g2 < 4; g2++) {
        uint32_t br = (uint32_t)((wn + g2 * 16 + b_r) * RS + k0 + b_c) * 2;
        uint32_t rh[4], rl[4];
        ldsm_x4(rh, sb + 2 * TILE_B + br);
        ldsm_x4(rl, sb + 3 * TILE_B + br);
        bh[g2 * 2][0] = rh[0]; bh[g2 * 2][1] = rh[1];
        bh[g2 * 2 + 1][0] = rh[2]; bh[g2 * 2 + 1][1] = rh[3];
        bl[g2 * 2][0] = rl[0]; bl[g2 * 2][1] = rl[1];
        bl[g2 * 2 + 1][0] = rl[2]; bl[g2 * 2 + 1][1] = rl[3];
      }
#pragma unroll
      for (int f = 0; f < 2; f++)
#pragma unroll
        for (int g = 0; g < 8; g++) {
          mma16816(acc[f][g], ah[f], bh[g]);
          mma16816(acc[f][g], ah[f], bl[g]);
          mma16816(acc[f][g], al[f], bh[g]);
        }
    }
    __syncthreads();
  }

  // Epilogue: d0,d1 -> (row, col..col+1); d2,d3 -> (row+8, ...)
  const int gid = lane >> 2, tig = lane & 3;
#pragma unroll
  for (int f = 0; f < 2; f++) {
#pragma unroll
    for (int g = 0; g < 8; g++) {
      int row = m0 + wm + f * 16 + gid;
      int col = n0 + wn + g * 8 + tig * 2;
      *(float2*)(C + (size_t)row * N + col) = make_float2(acc[f][g][0], acc[f][g][1]);
      *(float2*)(C + (size_t)(row + 8) * N + col) = make_float2(acc[f][g][2], acc[f][g][3]);
    }
  }
}

// ---------------------------------------------------------------------------
// RoPE (interleaved pairs) on a region of g_QKV; row stride QKV_N.
// ---------------------------------------------------------------------------
__global__ void rope_kernel(float* __restrict__ X, int nheads, int total) {
  int idx = blockIdx.x * blockDim.x + threadIdx.x;
  if (idx >= total) return;
  int i = idx % (HD / 2);
  int tmp = idx / (HD / 2);
  int h = tmp % nheads;
  int s = tmp / nheads;
  float inv = 1.0f / powf(10000.0f, (2.0f * i) / (float)HD);
  float ang = (float)s * inv;
  float c = cosf(ang), sn = sinf(ang);
  float* p = X + (size_t)s * QKV_N + h * HD + 2 * i;
  float xr = p[0], xi = p[1];
  p[0] = xr * c - xi * sn;
  p[1] = xr * sn + xi * c;
}

// ---------------------------------------------------------------------------
// Flash-attention (fp32, online softmax). Reads fused QKV (stride QKV_N).
// Writes O as bf16 hi/lo split for the Wo GEMM.
// ---------------------------------------------------------------------------
#define BQ 64
#define BKV 64

__global__ __launch_bounds__(256) void attn_kernel(
    const float* __restrict__ QKV, __nv_bfloat16* __restrict__ Ohi,
    __nv_bfloat16* __restrict__ Olo) {
  extern __shared__ float sm[];
  float* Qs = sm;               // [HD][BQ]
  float* Ks = Qs + HD * BQ;     // [HD][BKV]
  float* Vs = Ks + HD * BKV;    // [BKV][HD]
  float* Ps = Vs + BKV * HD;    // [BKV][BQ]

  const int h = blockIdx.x;
  const int qt = blockIdx.y;
  const int kvh = h / NREP;
  const int q0 = qt * BQ;
  const int tid = threadIdx.x;
  const int tx = tid % 16;
  const int ty = tid / 16;

  for (int v = tid; v < BQ * (HD / 4); v += 256) {
    int q = v / (HD / 4);
    int d4 = (v % (HD / 4)) * 4;
    float4 f = *(const float4*)(QKV + (size_t)(q0 + q) * QKV_N + h * HD + d4);
    Qs[(d4 + 0) * BQ + q] = f.x;
    Qs[(d4 + 1) * BQ + q] = f.y;
    Qs[(d4 + 2) * BQ + q] = f.z;
    Qs[(d4 + 3) * BQ + q] = f.w;
  }

  float m_i[4], l_i[4], acc[4][4];
#pragma unroll
  for (int i = 0; i < 4; i++) {
    m_i[i] = -1e30f;
    l_i[i] = 0.0f;
#pragma unroll
    for (int j = 0; j < 4; j++) acc[i][j] = 0.0f;
  }

  const int kend = q0 + BQ;
  for (int k0 = 0; k0 < kend; k0 += BKV) {
    __syncthreads();
    for (int v = tid; v < BKV * (HD / 4); v += 256) {
      int kk = v / (HD / 4);
      int d4 = (v % (HD / 4)) * 4;
      float4 f = *(const float4*)(QKV + (size_t)(k0 + kk) * QKV_N + KCOL + kvh * HD + d4);
      Ks[(d4 + 0) * BKV + kk] = f.x;
      Ks[(d4 + 1) * BKV + kk] = f.y;
      Ks[(d4 + 2) * BKV + kk] = f.z;
      Ks[(d4 + 3) * BKV + kk] = f.w;
      *(float4*)&Vs[kk * HD + d4] =
          *(const float4*)(QKV + (size_t)(k0 + kk) * QKV_N + VCOL + kvh * HD + d4);
    }
    __syncthreads();

    float sc[4][4];
#pragma unroll
    for (int i = 0; i < 4; i++)
#pragma unroll
      for (int j = 0; j < 4; j++) sc[i][j] = 0.0f;

#pragma unroll 8
    for (int d = 0; d < HD; d++) {
      float4 av = *(const float4*)&Qs[d * BQ + ty * 4];
      float4 bv = *(const float4*)&Ks[d * BKV + tx * 4];
      float a[4] = {av.x, av.y, av.z, av.w};
      float b[4] = {bv.x, bv.y, bv.z, bv.w};
#pragma unroll
      for (int i = 0; i < 4; i++)
#pragma unroll
        for (int j = 0; j < 4; j++) sc[i][j] += a[i] * b[j];
    }

    const float scale = 0.125f;
#pragma unroll
    for (int i = 0; i < 4; i++)
#pragma unroll
      for (int j = 0; j < 4; j++) {
        int gq = q0 + ty * 4 + i;
        int gk = k0 + tx * 4 + j;
        sc[i][j] = (gk <= gq) ? sc[i][j] * scale : -1e30f;
      }

#pragma unroll
    for (int i = 0; i < 4; i++) {
      float mx = fmaxf(fmaxf(sc[i][0], sc[i][1]), fmaxf(sc[i][2], sc[i][3]));
#pragma unroll
      for (int off = 8; off >= 1; off >>= 1)
        mx = fmaxf(mx, __shfl_xor_sync(0xffffffffu, mx, off, 16));
      float m_new = fmaxf(m_i[i], mx);
      float corr = __expf(m_i[i] - m_new);
      m_i[i] = m_new;
      l_i[i] *= corr;
#pragma unroll
      for (int j = 0; j < 4; j++) acc[i][j] *= corr;
      float ps = 0.0f;
#pragma unroll
      for (int j = 0; j < 4; j++) {
        float p = __expf(sc[i][j] - m_new);
        sc[i][j] = p;
        ps += p;
      }
#pragma unroll
      for (int off = 8; off >= 1; off >>= 1)
        ps += __shfl_xor_sync(0xffffffffu, ps, off, 16);
      l_i[i] += ps;
    }

#pragma unroll
    for (int i = 0; i < 4; i++)
#pragma unroll
      for (int j = 0; j < 4; j++)
        Ps[(tx * 4 + j) * BQ + (ty * 4 + i)] = sc[i][j];
    __syncthreads();

#pragma unroll 8
    for (int k = 0; k < BKV; k++) {
      float4 pv = *(const float4*)&Ps[k * BQ + ty * 4];
      float4 vv = *(const float4*)&Vs[k * HD + tx * 4];
      float pa[4] = {pv.x, pv.y, pv.z, pv.w};
      float vb[4] = {vv.x, vv.y, vv.z, vv.w};
#pragma unroll
      for (int i = 0; i < 4; i++)
#pragma unroll
        for (int j = 0; j < 4; j++) acc[i][j] += pa[i] * vb[j];
    }
  }

#pragma unroll
  for (int i = 0; i < 4; i++) {
    float inv_l = 1.0f / l_i[i];
    int gq = q0 + ty * 4 + i;
    size_t base = (size_t)gq * (H * HD) + h * HD + tx * 4;
#pragma unroll
    for (int j = 0; j < 4; j++) {
      float x = acc[i][j] * inv_l;
      __nv_bfloat16 hh, ll;
      split2(x, hh, ll);
      Ohi[base + j] = hh;
      Olo[base + j] = ll;
    }
  }
}

// ---------------------------------------------------------------------------
// Launch
// ---------------------------------------------------------------------------
extern "C" void kernel_launch(void* const* d_in, const int* in_sizes, int n_in,
                              void* d_out, int out_size) {
  const float* hs = (const float*)d_in[0];  // [1,2048,2048]
  const float* Wq = (const float*)d_in[1];  // [2048,2048]
  const float* Wk = (const float*)d_in[2];  // [2048,512]
  const float* Wv = (const float*)d_in[3];  // [2048,512]
  const float* Wo = (const float*)d_in[4];  // [2048,2048]
  float* out = (float*)d_out;               // [1,2048,2048]

  float* QKVp;
  __nv_bfloat16 *Xhi, *Xlo, *Ohi, *Olo, *WqkvThi, *WqkvTlo, *WoThi, *WoTlo;
  cudaGetSymbolAddress((void**)&QKVp, g_QKV);
  cudaGetSymbolAddress((void**)&Xhi, g_Xhi);
  cudaGetSymbolAddress((void**)&Xlo, g_Xlo);
  cudaGetSymbolAddress((void**)&Ohi, g_Ohi);
  cudaGetSymbolAddress((void**)&Olo, g_Olo);
  cudaGetSymbolAddress((void**)&WqkvThi, g_WqkvThi);
  cudaGetSymbolAddress((void**)&WqkvTlo, g_WqkvTlo);
  cudaGetSymbolAddress((void**)&WoThi, g_WoThi);
  cudaGetSymbolAddress((void**)&WoTlo, g_WoTlo);

  // 1. Split activations into bf16 hi/lo
  {
    int n4 = S * D / 4;
    split_kernel<<<(n4 + 255) / 256, 256>>>(hs, Xhi, Xlo, n4);
  }

  // 2. Transpose + split weights: Wq/Wk/Wv fused into WqkvT [3072][2048]
  {
    dim3 blk(32, 8);
    transpose_split_kernel<<<dim3(D / 32, D / 32), blk>>>(Wq, WqkvThi, WqkvTlo, D, D);
    transpose_split_kernel<<<dim3(512 / 32, D / 32), blk>>>(
        Wk, WqkvThi + (size_t)KCOL * D, WqkvTlo + (size_t)KCOL * D, 512, D);
    transpose_split_kernel<<<dim3(512 / 32, D / 32), blk>>>(
        Wv, WqkvThi + (size_t)VCOL * D, WqkvTlo + (size_t)VCOL * D, 512, D);
    transpose_split_kernel<<<dim3(D / 32, D / 32), blk>>>(Wo, WoThi, WoTlo, D, D);
  }

  cudaFuncSetAttribute(gemm_bf16x3_kernel,
                       cudaFuncAttributeMaxDynamicSharedMemorySize, GEMM_SMEM);

  // 3. Fused QKV projection GEMM: [2048,2048] @ [2048,3072]
  {
    dim3 grid(QKV_N / GBN, S / GBM);  // 24 x 16
    gemm_bf16x3_kernel<<<grid, 256, GEMM_SMEM>>>(Xhi, Xlo, WqkvThi, WqkvTlo,
                                                 QKVp, S, QKV_N, D);
  }

  // 4. RoPE on Q and K regions of fused QKV
  {
    int totq = S * H * (HD / 2);
    int totk = S * KVH * (HD / 2);
    rope_kernel<<<(totq + 255) / 256, 256>>>(QKVp, H, totq);
    rope_kernel<<<(totk + 255) / 256, 256>>>(QKVp + KCOL, KVH, totk);
  }

  // 5. Attention (fp32), writes bf16 hi/lo O
  {
    int smem_bytes = (HD * BQ + HD * BKV + BKV * HD + BKV * BQ) * sizeof(float);
    cudaFuncSetAttribute(attn_kernel, cudaFuncAttributeMaxDynamicSharedMemorySize,
                         smem_bytes);
    dim3 grid(H, S / BQ);
    attn_kernel<<<grid, 256, smem_bytes>>>(QKVp, Ohi, Olo);
  }

  // 6. Output projection GEMM: [2048,2048] @ [2048,2048]
  {
    dim3 grid(D / GBN, S / GBM);  // 16 x 16
    gemm_bf16x3_kernel<<<grid, 256, GEMM_SMEM>>>(Ohi, Olo, WoThi, WoTlo, out,
                                                 S, D, D);
  }
}

// round 4
// speedup vs baseline: 3.3963x; 1.8878x over previous
#include <cuda_runtime.h>
#include <cuda_bf16.h>
#include <cstdint>
#include <math.h>

#define S 2048
#define D 2048
#define H 32
#define KVH 8
#define HD 64
#define NREP (H / KVH)
#define QKV_N 3072
#define KCOL 2048
#define VCOL 2560

// ---------------------------------------------------------------------------
// Device-global scratch
// ---------------------------------------------------------------------------
__device__ float g_QKV[S * QKV_N];
__device__ __nv_bfloat16 g_Xhi[S * D], g_Xlo[S * D];
__device__ __nv_bfloat16 g_Ohi[S * D], g_Olo[S * D];
__device__ __nv_bfloat16 g_WqkvThi[QKV_N * D], g_WqkvTlo[QKV_N * D];
__device__ __nv_bfloat16 g_WoThi[D * D], g_WoTlo[D * D];
__device__ __nv_bfloat16 g_Qhi[S * H * HD], g_Qlo[S * H * HD];
__device__ __nv_bfloat16 g_Khi[S * KVH * HD], g_Klo[S * KVH * HD];
__device__ __nv_bfloat16 g_Vhi[S * KVH * HD], g_Vlo[S * KVH * HD];

// ---------------------------------------------------------------------------
// Helpers (portable sm_80+ tensor ISA)
// ---------------------------------------------------------------------------
__device__ __forceinline__ uint32_t smem_u32(const void* p) {
  uint32_t a;
  asm("{ .reg .u64 t; cvta.to.shared.u64 t, %1; cvt.u32.u64 %0, t; }"
      : "=r"(a) : "l"(p));
  return a;
}

__device__ __forceinline__ void ldsm_x4(uint32_t* r, uint32_t addr) {
  asm volatile(
      "ldmatrix.sync.aligned.m8n8.x4.shared.b16 {%0,%1,%2,%3}, [%4];"
      : "=r"(r[0]), "=r"(r[1]), "=r"(r[2]), "=r"(r[3]) : "r"(addr));
}

__device__ __forceinline__ void ldsm_x4_trans(uint32_t* r, uint32_t addr) {
  asm volatile(
      "ldmatrix.sync.aligned.m8n8.x4.trans.shared.b16 {%0,%1,%2,%3}, [%4];"
      : "=r"(r[0]), "=r"(r[1]), "=r"(r[2]), "=r"(r[3]) : "r"(addr));
}

__device__ __forceinline__ void mma16816(float* d, const uint32_t* a,
                                         const uint32_t* b) {
  asm volatile(
      "mma.sync.aligned.m16n8k16.row.col.f32.bf16.bf16.f32 "
      "{%0,%1,%2,%3}, {%4,%5,%6,%7}, {%8,%9}, {%0,%1,%2,%3};"
      : "+f"(d[0]), "+f"(d[1]), "+f"(d[2]), "+f"(d[3])
      : "r"(a[0]), "r"(a[1]), "r"(a[2]), "r"(a[3]), "r"(b[0]), "r"(b[1]));
}

__device__ __forceinline__ void cp_async16(uint32_t saddr, const void* gptr) {
  asm volatile("cp.async.cg.shared.global [%0], [%1], 16;" ::
                   "r"(saddr), "l"(__cvta_generic_to_global(gptr)));
}
#define CP_COMMIT() asm volatile("cp.async.commit_group;" ::: "memory")
#define CP_WAIT0() asm volatile("cp.async.wait_group 0;" ::: "memory")

// fast 2^x on the FMA pipe (x <= 0). |rel err| < 2e-5.
__device__ __forceinline__ float exp2_poly(float x) {
  x = fmaxf(x, -126.0f);
  float fl = floorf(x);
  float f = x - fl;
  float p = 1.5403530393e-4f;
  p = fmaf(p, f, 1.3333558146e-3f);
  p = fmaf(p, f, 9.6181291076e-3f);
  p = fmaf(p, f, 5.5504108665e-2f);
  p = fmaf(p, f, 2.4022650696e-1f);
  p = fmaf(p, f, 6.9314718056e-1f);
  p = fmaf(p, f, 1.0f);
  return p * __int_as_float(((int)fl + 127) << 23);
}

__device__ __forceinline__ void split2(float x, __nv_bfloat16& h, __nv_bfloat16& l) {
  h = __float2bfloat16(x);
  l = __float2bfloat16(x - __bfloat162float(h));
}

// pack (x low, y high) into bf16x2 hi reg + residual lo reg
__device__ __forceinline__ void split_pack2(float x, float y, uint32_t& h,
                                            uint32_t& l) {
  __nv_bfloat162 hb = __floats2bfloat162_rn(x, y);
  float xr = x - __bfloat162float(hb.x);
  float yr = y - __bfloat162float(hb.y);
  __nv_bfloat162 lb = __floats2bfloat162_rn(xr, yr);
  h = *reinterpret_cast<uint32_t*>(&hb);
  l = *reinterpret_cast<uint32_t*>(&lb);
}

// ---------------------------------------------------------------------------
// fp32 -> bf16 hi/lo split (activations)
// ---------------------------------------------------------------------------
__global__ void split_kernel(const float* __restrict__ in,
                             __nv_bfloat16* __restrict__ hi,
                             __nv_bfloat16* __restrict__ lo, int n4) {
  int i = blockIdx.x * blockDim.x + threadIdx.x;
  if (i >= n4) return;
  float4 v = ((const float4*)in)[i];
  __nv_bfloat16 h0, l0, h1, l1, h2, l2, h3, l3;
  split2(v.x, h0, l0); split2(v.y, h1, l1);
  split2(v.z, h2, l2); split2(v.w, h3, l3);
  __nv_bfloat162* hp = (__nv_bfloat162*)hi;
  __nv_bfloat162* lp = (__nv_bfloat162*)lo;
  hp[i * 2 + 0] = __halves2bfloat162(h0, h1);
  hp[i * 2 + 1] = __halves2bfloat162(h2, h3);
  lp[i * 2 + 0] = __halves2bfloat162(l0, l1);
  lp[i * 2 + 1] = __halves2bfloat162(l2, l3);
}

__global__ void transpose_split_kernel(const float* __restrict__ W,
                                       __nv_bfloat16* __restrict__ Thi,
                                       __nv_bfloat16* __restrict__ Tlo,
                                       int N, int K) {
  __shared__ float t[32][33];
  int n0 = blockIdx.x * 32, k0 = blockIdx.y * 32;
  int tx = threadIdx.x, ty = threadIdx.y;
#pragma unroll
  for (int i = 0; i < 4; i++)
    t[ty + i * 8][tx] = W[(size_t)(k0 + ty + i * 8) * N + n0 + tx];
  __syncthreads();
#pragma unroll
  for (int i = 0; i < 4; i++) {
    int n = ty + i * 8;
    float x = t[tx][n];
    __nv_bfloat16 h, l;
    split2(x, h, l);
    size_t o = (size_t)(n0 + n) * K + k0 + tx;
    Thi[o] = h;
    Tlo[o] = l;
  }
}

// ---------------------------------------------------------------------------
// bf16x3-split GEMM (same as R3, verified)
// ---------------------------------------------------------------------------
#define GBM 128
#define GBN 128
#define GKC 32
#define RS 40
#define TILE_B (128 * RS * 2)
#define STAGE_B (4 * TILE_B)
#define GEMM_SMEM (2 * STAGE_B)

__global__ __launch_bounds__(256) void gemm_bf16x3_kernel(
    const __nv_bfloat16* __restrict__ Ahi, const __nv_bfloat16* __restrict__ Alo,
    const __nv_bfloat16* __restrict__ Bhi, const __nv_bfloat16* __restrict__ Blo,
    float* __restrict__ C, int M, int N, int K) {
  extern __shared__ char smem[];
  const uint32_t sbase = smem_u32(smem);
  const int tid = threadIdx.x;
  const int wid = tid >> 5;
  const int lane = tid & 31;
  const int m0 = blockIdx.y * GBM;
  const int n0 = blockIdx.x * GBN;
  const int NC = K / GKC;

  const int wm = (wid & 3) * 32;
  const int wn = (wid >> 2) * 64;
  const int lrow = lane & 7;
  const int ltile = lane >> 3;
  const int a_r = (ltile & 1) * 8 + lrow;
  const int a_c = (ltile >> 1) * 8;
  const int b_r = (ltile >> 1) * 8 + lrow;
  const int b_c = (ltile & 1) * 8;

  const __nv_bfloat16* gA[2] = {Ahi + (size_t)m0 * K, Alo + (size_t)m0 * K};
  const __nv_bfloat16* gB[2] = {Bhi + (size_t)n0 * K, Blo + (size_t)n0 * K};

  auto load_stage = [&](int stg, int chunk) {
    const int kc = chunk * GKC;
    uint32_t sb = sbase + stg * STAGE_B;
#pragma unroll
    for (int t = 0; t < 4; t++) {
      const __nv_bfloat16* gp = (t < 2) ? gA[t] : gB[t - 2];
#pragma unroll
      for (int i = 0; i < 2; i++) {
        int v = tid + i * 256;
        int r = v >> 2;
        int c = (v & 3) * 8;
        cp_async16(sb + t * TILE_B + (uint32_t)(r * RS + c) * 2,
                   gp + (size_t)r * K + kc + c);
      }
    }
    CP_COMMIT();
  };

  float acc[2][8][4];
#pragma unroll
  for (int f = 0; f < 2; f++)
#pragma unroll
    for (int g = 0; g < 8; g++)
#pragma unroll
      for (int x = 0; x < 4; x++) acc[f][g][x] = 0.0f;

  load_stage(0, 0);

  for (int c = 0; c < NC; c++) {
    CP_WAIT0();
    __syncthreads();
    if (c + 1 < NC) load_stage((c + 1) & 1, c + 1);

    uint32_t sb = sbase + (c & 1) * STAGE_B;
#pragma unroll
    for (int kk = 0; kk < 2; kk++) {
      const int k0 = kk * 16;
      uint32_t ah[2][4], al[2][4], bh[8][2], bl[8][2];
#pragma unroll
      for (int f = 0; f < 2; f++) {
        uint32_t ar = (uint32_t)((wm + f * 16 + a_r) * RS + k0 + a_c) * 2;
        ldsm_x4(ah[f], sb + 0 * TILE_B + ar);
        ldsm_x4(al[f], sb + 1 * TILE_B + ar);
      }
#pragma unroll
      for (int g2 = 0; g2 < 4; g2++) {
        uint32_t br = (uint32_t)((wn + g2 * 16 + b_r) * RS + k0 + b_c) * 2;
        uint32_t rh[4], rl[4];
        ldsm_x4(rh, sb + 2 * TILE_B + br);
        ldsm_x4(rl, sb + 3 * TILE_B + br);
        bh[g2 * 2][0] = rh[0]; bh[g2 * 2][1] = rh[1];
        bh[g2 * 2 + 1][0] = rh[2]; bh[g2 * 2 + 1][1] = rh[3];
        bl[g2 * 2][0] = rl[0]; bl[g2 * 2][1] = rl[1];
        bl[g2 * 2 + 1][0] = rl[2]; bl[g2 * 2 + 1][1] = rl[3];
      }
#pragma unroll
      for (int f = 0; f < 2; f++)
#pragma unroll
        for (int g = 0; g < 8; g++) {
          mma16816(acc[f][g], ah[f], bh[g]);
          mma16816(acc[f][g], ah[f], bl[g]);
          mma16816(acc[f][g], al[f], bh[g]);
        }
    }
    __syncthreads();
  }

  const int gid = lane >> 2, tig = lane & 3;
#pragma unroll
  for (int f = 0; f < 2; f++) {
#pragma unroll
    for (int g = 0; g < 8; g++) {
      int row = m0 + wm + f * 16 + gid;
      int col = n0 + wn + g * 8 + tig * 2;
      *(float2*)(C + (size_t)row * N + col) = make_float2(acc[f][g][0], acc[f][g][1]);
      *(float2*)(C + (size_t)(row + 8) * N + col) = make_float2(acc[f][g][2], acc[f][g][3]);
    }
  }
}

// ---------------------------------------------------------------------------
// RoPE + split: g_QKV fp32 -> Q/K (roped) and V, all bf16 hi/lo, compact rows
// ---------------------------------------------------------------------------
__global__ void rope_split_kernel(const float* __restrict__ QKV) {
  const int QP = S * H * HD / 2;
  const int KP = S * KVH * HD / 2;
  int idx = blockIdx.x * blockDim.x + threadIdx.x;
  if (idx >= QP + 2 * KP) return;

  float xr, xi;
  __nv_bfloat162* hi_dst;
  __nv_bfloat162* lo_dst;

  if (idx < QP) {
    int i = idx & 31;
    int tmp = idx >> 5;
    int hh = tmp % H;
    int s = tmp / H;
    const float* p = QKV + (size_t)s * QKV_N + hh * HD + 2 * i;
    float a = p[0], b = p[1];
    float inv = 1.0f / powf(10000.0f, (2.0f * i) / (float)HD);
    float ang = (float)s * inv;
    float c = cosf(ang), sn = sinf(ang);
    xr = a * c - b * sn;
    xi = a * sn + b * c;
    size_t o = ((size_t)s * (H * HD) + hh * HD + 2 * i) / 2;
    hi_dst = (__nv_bfloat162*)g_Qhi + o;
    lo_dst = (__nv_bfloat162*)g_Qlo + o;
  } else if (idx < QP + KP) {
    int j = idx - QP;
    int i = j & 31;
    int tmp = j >> 5;
    int hh = tmp % KVH;
    int s = tmp / KVH;
    const float* p = QKV + (size_t)s * QKV_N + KCOL + hh * HD + 2 * i;
    float a = p[0], b = p[1];
    float inv = 1.0f / powf(10000.0f, (2.0f * i) / (float)HD);
    float ang = (float)s * inv;
    float c = cosf(ang), sn = sinf(ang);
    xr = a * c - b * sn;
    xi = a * sn + b * c;
    size_t o = ((size_t)s * (KVH * HD) + hh * HD + 2 * i) / 2;
    hi_dst = (__nv_bfloat162*)g_Khi + o;
    lo_dst = (__nv_bfloat162*)g_Klo + o;
  } else {
    int j = idx - QP - KP;
    int i = j & 31;
    int tmp = j >> 5;
    int hh = tmp % KVH;
    int s = tmp / KVH;
    const float* p = QKV + (size_t)s * QKV_N + VCOL + hh * HD + 2 * i;
    xr = p[0];
    xi = p[1];
    size_t o = ((size_t)s * (KVH * HD) + hh * HD + 2 * i) / 2;
    hi_dst = (__nv_bfloat162*)g_Vhi + o;
    lo_dst = (__nv_bfloat162*)g_Vlo + o;
  }

  __nv_bfloat16 h0, l0, h1, l1;
  split2(xr, h0, l0);
  split2(xi, h1, l1);
  *hi_dst = __halves2bfloat162(h0, h1);
  *lo_dst = __halves2bfloat162(l0, l1);
}

// ---------------------------------------------------------------------------
// Tensor-core flash attention (bf16x3 split QK and PV, poly exp2 softmax)
// Block: one head x 128 q rows. 8 warps, warp = m16. KV tile 64, double buf.
// ---------------------------------------------------------------------------
#define ABQ 128
#define ABKV 64
#define ARS 72
#define Q_ELEMS (ABQ * ARS)         // 9216
#define KV_TILE (ABKV * ARS)        // 4608
#define KV_STAGE (4 * KV_TILE)      // 18432
#define ATT_SMEM ((2 * Q_ELEMS + 2 * KV_STAGE) * 2)  // 110592 B

__global__ __launch_bounds__(256) void attn_mma_kernel(
    const __nv_bfloat16* __restrict__ Qhi, const __nv_bfloat16* __restrict__ Qlo,
    const __nv_bfloat16* __restrict__ Khi, const __nv_bfloat16* __restrict__ Klo,
    const __nv_bfloat16* __restrict__ Vhi, const __nv_bfloat16* __restrict__ Vlo,
    __nv_bfloat16* __restrict__ Ohi, __nv_bfloat16* __restrict__ Olo) {
  extern __shared__ char sbuf[];
  const uint32_t sbase = smem_u32(sbuf);
  const int tid = threadIdx.x;
  const int wid = tid >> 5;
  const int lane = tid & 31;
  const int h = blockIdx.x;
  const int kvh = h / NREP;
  const int q0 = ((int)gridDim.y - 1 - (int)blockIdx.y) * ABQ;  // big tiles first
  const int wm = wid * 16;

  const int lrow = lane & 7;
  const int ltile = lane >> 3;
  const int a_r = (ltile & 1) * 8 + lrow;   // A/V tile row (non-trans / trans)
  const int a_c = (ltile >> 1) * 8;
  const int b_r = (ltile >> 1) * 8 + lrow;  // B (K) tile row
  const int b_c = (ltile & 1) * 8;
  const int gid = lane >> 2, tig = lane & 3;

  const uint32_t qhi_s = sbase;
  const uint32_t qlo_s = sbase + Q_ELEMS * 2;

  // ---- load Q tile (hi/lo) ----
#pragma unroll
  for (int i = 0; i < 4; i++) {
    int v = tid + i * 256;  // 0..1023
    int r = v >> 3, c = v & 7;
    size_t g = (size_t)(q0 + r) * (H * HD) + h * HD + c * 8;
    uint32_t so = (uint32_t)(r * ARS + c * 8) * 2;
    cp_async16(qhi_s + so, Qhi + g);
    cp_async16(qlo_s + so, Qlo + g);
  }

  auto load_kv = [&](int stg, int kv0) {
    uint32_t base = sbase + (2 * Q_ELEMS + stg * KV_STAGE) * 2;
#pragma unroll
    for (int i = 0; i < 2; i++) {
      int v = tid + i * 256;  // 0..511
      int r = v >> 3, c = v & 7;
      size_t g = (size_t)(kv0 + r) * (KVH * HD) + kvh * HD + c * 8;
      uint32_t so = (uint32_t)(r * ARS + c * 8) * 2;
      cp_async16(base + 0 * KV_TILE * 2 + so, Khi + g);
      cp_async16(base + 1 * KV_TILE * 2 + so, Klo + g);
      cp_async16(base + 2 * KV_TILE * 2 + so, Vhi + g);
      cp_async16(base + 3 * KV_TILE * 2 + so, Vlo + g);
    }
    CP_COMMIT();
  };

  load_kv(0, 0);

  const int ntiles = (q0 + ABQ) / ABKV;
  float m_[2] = {-1e30f, -1e30f};
  float l_[2] = {0.0f, 0.0f};
  float o[8][4];
#pragma unroll
  for (int nf = 0; nf < 8; nf++)
#pragma unroll
    for (int j = 0; j < 4; j++) o[nf][j] = 0.0f;

  const float SCL = 0.18033688011112042f;  // (1/8) * log2(e)
  const int row0 = q0 + wm + gid;

  for (int t = 0; t < ntiles; t++) {
    const int kv0 = t * ABKV;
    CP_WAIT0();
    __syncthreads();
    if (t + 1 < ntiles) load_kv((t + 1) & 1, kv0 + ABKV);

    const uint32_t kvb = sbase + (2 * Q_ELEMS + (t & 1) * KV_STAGE) * 2;

    // ---- S = Q K^T (bf16x3) ----
    float sc[8][4];
#pragma unroll
    for (int nf = 0; nf < 8; nf++)
#pragma unroll
      for (int j = 0; j < 4; j++) sc[nf][j] = 0.0f;

#pragma unroll
    for (int ks = 0; ks < 4; ks++) {
      const int k0 = ks * 16;
      uint32_t ah[4], al[4];
      uint32_t ar = (uint32_t)((wm + a_r) * ARS + k0 + a_c) * 2;
      ldsm_x4(ah, qhi_s + ar);
      ldsm_x4(al, qlo_s + ar);
#pragma unroll
      for (int ng = 0; ng < 4; ng++) {
        uint32_t br = kvb + (uint32_t)((ng * 16 + b_r) * ARS + k0 + b_c) * 2;
        uint32_t rh[4], rl[4];
        ldsm_x4(rh, br);
        ldsm_x4(rl, br + KV_TILE * 2);
        mma16816(sc[ng * 2], ah, rh);
        mma16816(sc[ng * 2], ah, rl);
        mma16816(sc[ng * 2], al, rh);
        mma16816(sc[ng * 2 + 1], ah, rh + 2);
        mma16816(sc[ng * 2 + 1], ah, rl + 2);
        mma16816(sc[ng * 2 + 1], al, rh + 2);
      }
    }

    // ---- scale + causal mask ----
    const bool nomask = (kv0 + ABKV - 1 <= q0 + wm);
    if (nomask) {
#pragma unroll
      for (int nf = 0; nf < 8; nf++)
#pragma unroll
        for (int j = 0; j < 4; j++) sc[nf][j] *= SCL;
    } else {
#pragma unroll
      for (int nf = 0; nf < 8; nf++) {
        int col = kv0 + nf * 8 + tig * 2;
#pragma unroll
        for (int j = 0; j < 4; j++) {
          int cc = col + (j & 1);
          int rr = row0 + ((j >> 1) << 3);
          sc[nf][j] = (cc <= rr) ? sc[nf][j] * SCL : -1e30f;
        }
      }
    }

    // ---- online softmax (base 2, poly exp) ----
    float mx0 = -1e30f, mx1 = -1e30f;
#pragma unroll
    for (int nf = 0; nf < 8; nf++) {
      mx0 = fmaxf(mx0, fmaxf(sc[nf][0], sc[nf][1]));
      mx1 = fmaxf(mx1, fmaxf(sc[nf][2], sc[nf][3]));
    }
    mx0 = fmaxf(mx0, __shfl_xor_sync(0xffffffffu, mx0, 1));
    mx0 = fmaxf(mx0, __shfl_xor_sync(0xffffffffu, mx0, 2));
    mx1 = fmaxf(mx1, __shfl_xor_sync(0xffffffffu, mx1, 1));
    mx1 = fmaxf(mx1, __shfl_xor_sync(0xffffffffu, mx1, 2));
    float mn0 = fmaxf(m_[0], mx0);
    float mn1 = fmaxf(m_[1], mx1);
    float c0 = exp2_poly(m_[0] - mn0);
    float c1 = exp2_poly(m_[1] - mn1);
    m_[0] = mn0;
    m_[1] = mn1;

    float s0 = 0.0f, s1 = 0.0f;
#pragma unroll
    for (int nf = 0; nf < 8; nf++) {
      float p0 = exp2_poly(sc[nf][0] - mn0);
      float p1 = exp2_poly(sc[nf][1] - mn0);
      float p2 = exp2_poly(sc[nf][2] - mn1);
      float p3 = exp2_poly(sc[nf][3] - mn1);
      sc[nf][0] = p0; sc[nf][1] = p1; sc[nf][2] = p2; sc[nf][3] = p3;
      s0 += p0 + p1;
      s1 += p2 + p3;
    }
    l_[0] = l_[0] * c0 + s0;  // thread-partial; quad-reduced at end
    l_[1] = l_[1] * c1 + s1;
#pragma unroll
    for (int nf = 0; nf < 8; nf++) {
      o[nf][0] *= c0; o[nf][1] *= c0;
      o[nf][2] *= c1; o[nf][3] *= c1;
    }

    // ---- O += P V (bf16x3; P split in regs, V via ldsm.trans) ----
    const uint32_t vhb = kvb + 2 * KV_TILE * 2;
#pragma unroll
    for (int ks = 0; ks < 4; ks++) {
      uint32_t phi[4], plo[4];
      split_pack2(sc[2 * ks][0], sc[2 * ks][1], phi[0], plo[0]);
      split_pack2(sc[2 * ks][2], sc[2 * ks][3], phi[1], plo[1]);
      split_pack2(sc[2 * ks + 1][0], sc[2 * ks + 1][1], phi[2], plo[2]);
      split_pack2(sc[2 * ks + 1][2], sc[2 * ks + 1][3], phi[3], plo[3]);
#pragma unroll
      for (int dg = 0; dg < 4; dg++) {
        uint32_t va = vhb + (uint32_t)((ks * 16 + a_r) * ARS + dg * 16 + a_c) * 2;
        uint32_t vh[4], vl[4];
        ldsm_x4_trans(vh, va);
        ldsm_x4_trans(vl, va + KV_TILE * 2);
        mma16816(o[dg * 2], phi, vh);
        mma16816(o[dg * 2], phi, vl);
        mma16816(o[dg * 2], plo, vh);
        mma16816(o[dg * 2 + 1], phi, vh + 2);
        mma16816(o[dg * 2 + 1], phi, vl + 2);
        mma16816(o[dg * 2 + 1], plo, vh + 2);
      }
    }
  }

  // ---- epilogue ----
  l_[0] += __shfl_xor_sync(0xffffffffu, l_[0], 1);
  l_[0] += __shfl_xor_sync(0xffffffffu, l_[0], 2);
  l_[1] += __shfl_xor_sync(0xffffffffu, l_[1], 1);
  l_[1] += __shfl_xor_sync(0xffffffffu, l_[1], 2);
  float inv0 = 1.0f / l_[0];
  float inv1 = 1.0f / l_[1];

#pragma unroll
  for (int nf = 0; nf < 8; nf++) {
    int col = h * HD + nf * 8 + tig * 2;
    uint32_t hreg, lreg;
    split_pack2(o[nf][0] * inv0, o[nf][1] * inv0, hreg, lreg);
    *(uint32_t*)(Ohi + (size_t)row0 * (H * HD) + col) = hreg;
    *(uint32_t*)(Olo + (size_t)row0 * (H * HD) + col) = lreg;
    split_pack2(o[nf][2] * inv1, o[nf][3] * inv1, hreg, lreg);
    *(uint32_t*)(Ohi + (size_t)(row0 + 8) * (H * HD) + col) = hreg;
    *(uint32_t*)(Olo + (size_t)(row0 + 8) * (H * HD) + col) = lreg;
  }
}

// ---------------------------------------------------------------------------
// Launch
// ---------------------------------------------------------------------------
extern "C" void kernel_launch(void* const* d_in, const int* in_sizes, int n_in,
                              void* d_out, int out_size) {
  const float* hs = (const float*)d_in[0];
  const float* Wq = (const float*)d_in[1];
  const float* Wk = (const float*)d_in[2];
  const float* Wv = (const float*)d_in[3];
  const float* Wo = (const float*)d_in[4];
  float* out = (float*)d_out;

  float* QKVp;
  __nv_bfloat16 *Xhi, *Xlo, *Ohi, *Olo, *WqkvThi, *WqkvTlo, *WoThi, *WoTlo;
  __nv_bfloat16 *Qhi, *Qlo, *Khi, *Klo, *Vhi, *Vlo;
  cudaGetSymbolAddress((void**)&QKVp, g_QKV);
  cudaGetSymbolAddress((void**)&Xhi, g_Xhi);
  cudaGetSymbolAddress((void**)&Xlo, g_Xlo);
  cudaGetSymbolAddress((void**)&Ohi, g_Ohi);
  cudaGetSymbolAddress((void**)&Olo, g_Olo);
  cudaGetSymbolAddress((void**)&WqkvThi, g_WqkvThi);
  cudaGetSymbolAddress((void**)&WqkvTlo, g_WqkvTlo);
  cudaGetSymbolAddress((void**)&WoThi, g_WoThi);
  cudaGetSymbolAddress((void**)&WoTlo, g_WoTlo);
  cudaGetSymbolAddress((void**)&Qhi, g_Qhi);
  cudaGetSymbolAddress((void**)&Qlo, g_Qlo);
  cudaGetSymbolAddress((void**)&Khi, g_Khi);
  cudaGetSymbolAddress((void**)&Klo, g_Klo);
  cudaGetSymbolAddress((void**)&Vhi, g_Vhi);
  cudaGetSymbolAddress((void**)&Vlo, g_Vlo);

  // 1. split activations
  {
    int n4 = S * D / 4;
    split_kernel<<<(n4 + 255) / 256, 256>>>(hs, Xhi, Xlo, n4);
  }

  // 2. transpose + split weights
  {
    dim3 blk(32, 8);
    transpose_split_kernel<<<dim3(D / 32, D / 32), blk>>>(Wq, WqkvThi, WqkvTlo, D, D);
    transpose_split_kernel<<<dim3(512 / 32, D / 32), blk>>>(
        Wk, WqkvThi + (size_t)KCOL * D, WqkvTlo + (size_t)KCOL * D, 512, D);
    transpose_split_kernel<<<dim3(512 / 32, D / 32), blk>>>(
        Wv, WqkvThi + (size_t)VCOL * D, WqkvTlo + (size_t)VCOL * D, 512, D);
    transpose_split_kernel<<<dim3(D / 32, D / 32), blk>>>(Wo, WoThi, WoTlo, D, D);
  }

  cudaFuncSetAttribute(gemm_bf16x3_kernel,
                       cudaFuncAttributeMaxDynamicSharedMemorySize, GEMM_SMEM);

  // 3. fused QKV projection
  {
    dim3 grid(QKV_N / GBN, S / GBM);
    gemm_bf16x3_kernel<<<grid, 256, GEMM_SMEM>>>(Xhi, Xlo, WqkvThi, WqkvTlo,
                                                 QKVp, S, QKV_N, D);
  }

  // 4. RoPE + split Q/K/V to bf16 hi/lo
  {
    int total = S * H * HD / 2 + 2 * (S * KVH * HD / 2);
    rope_split_kernel<<<(total + 255) / 256, 256>>>(QKVp);
  }

  // 5. tensor-core flash attention
  {
    cudaFuncSetAttribute(attn_mma_kernel,
                         cudaFuncAttributeMaxDynamicSharedMemorySize, ATT_SMEM);
    dim3 grid(H, S / ABQ);  // 32 x 16
    attn_mma_kernel<<<grid, 256, ATT_SMEM>>>(Qhi, Qlo, Khi, Klo, Vhi, Vlo,
                                             Ohi, Olo);
  }

  // 6. output projection
  {
    dim3 grid(D / GBN, S / GBM);
    gemm_bf16x3_kernel<<<grid, 256, GEMM_SMEM>>>(Ohi, Olo, WoThi, WoTlo, out,
                                                 S, D, D);
  }
}

// round 5
// speedup vs baseline: 3.9920x; 1.1754x over previous
#include <cuda_runtime.h>
#include <cuda_bf16.h>
#include <cuda_fp16.h>
#include <cstdint>
#include <math.h>

#define S 2048
#define D 2048
#define H 32
#define KVH 8
#define HD 64
#define NREP (H / KVH)
#define QKV_N 3072
#define KCOL 2048
#define VCOL 2560

// ---------------------------------------------------------------------------
// Device-global scratch
// ---------------------------------------------------------------------------
__device__ float g_QKV[S * QKV_N];
__device__ __nv_bfloat16 g_Xhi[S * D], g_Xlo[S * D];
__device__ __nv_bfloat16 g_WqkvThi[QKV_N * D], g_WqkvTlo[QKV_N * D];
__device__ __nv_bfloat16 g_Qhi[S * H * HD], g_Qlo[S * H * HD];
__device__ __nv_bfloat16 g_Khi[S * KVH * HD], g_Klo[S * KVH * HD];
__device__ __nv_bfloat16 g_Vhi[S * KVH * HD], g_Vlo[S * KVH * HD];
__device__ __half g_O16[S * D];      // attention output, fp16 (linear path)
__device__ __half g_WoT16[D * D];    // Wo transposed, fp16

// ---------------------------------------------------------------------------
// Helpers (portable sm_80+ tensor ISA)
// ---------------------------------------------------------------------------
__device__ __forceinline__ uint32_t smem_u32(const void* p) {
  uint32_t a;
  asm("{ .reg .u64 t; cvta.to.shared.u64 t, %1; cvt.u32.u64 %0, t; }"
      : "=r"(a) : "l"(p));
  return a;
}

__device__ __forceinline__ void ldsm_x4(uint32_t* r, uint32_t addr) {
  asm volatile(
      "ldmatrix.sync.aligned.m8n8.x4.shared.b16 {%0,%1,%2,%3}, [%4];"
      : "=r"(r[0]), "=r"(r[1]), "=r"(r[2]), "=r"(r[3]) : "r"(addr));
}

__device__ __forceinline__ void ldsm_x4_trans(uint32_t* r, uint32_t addr) {
  asm volatile(
      "ldmatrix.sync.aligned.m8n8.x4.trans.shared.b16 {%0,%1,%2,%3}, [%4];"
      : "=r"(r[0]), "=r"(r[1]), "=r"(r[2]), "=r"(r[3]) : "r"(addr));
}

__device__ __forceinline__ void mma16816(float* d, const uint32_t* a,
                                         const uint32_t* b) {
  asm volatile(
      "mma.sync.aligned.m16n8k16.row.col.f32.bf16.bf16.f32 "
      "{%0,%1,%2,%3}, {%4,%5,%6,%7}, {%8,%9}, {%0,%1,%2,%3};"
      : "+f"(d[0]), "+f"(d[1]), "+f"(d[2]), "+f"(d[3])
      : "r"(a[0]), "r"(a[1]), "r"(a[2]), "r"(a[3]), "r"(b[0]), "r"(b[1]));
}

__device__ __forceinline__ void mma16816h(float* d, const uint32_t* a,
                                          const uint32_t* b) {
  asm volatile(
      "mma.sync.aligned.m16n8k16.row.col.f32.f16.f16.f32 "
      "{%0,%1,%2,%3}, {%4,%5,%6,%7}, {%8,%9}, {%0,%1,%2,%3};"
      : "+f"(d[0]), "+f"(d[1]), "+f"(d[2]), "+f"(d[3])
      : "r"(a[0]), "r"(a[1]), "r"(a[2]), "r"(a[3]), "r"(b[0]), "r"(b[1]));
}

__device__ __forceinline__ void cp_async16(uint32_t saddr, const void* gptr) {
  asm volatile("cp.async.cg.shared.global [%0], [%1], 16;" ::
                   "r"(saddr), "l"(__cvta_generic_to_global(gptr)));
}
#define CP_COMMIT() asm volatile("cp.async.commit_group;" ::: "memory")
#define CP_WAIT0() asm volatile("cp.async.wait_group 0;" ::: "memory")

// fast 2^x on the FMA pipe (x <= 0). |rel err| < 2e-5.
__device__ __forceinline__ float exp2_poly(float x) {
  x = fmaxf(x, -126.0f);
  float fl = floorf(x);
  float f = x - fl;
  float p = 1.5403530393e-4f;
  p = fmaf(p, f, 1.3333558146e-3f);
  p = fmaf(p, f, 9.6181291076e-3f);
  p = fmaf(p, f, 5.5504108665e-2f);
  p = fmaf(p, f, 2.4022650696e-1f);
  p = fmaf(p, f, 6.9314718056e-1f);
  p = fmaf(p, f, 1.0f);
  return p * __int_as_float(((int)fl + 127) << 23);
}

__device__ __forceinline__ void split2(float x, __nv_bfloat16& h, __nv_bfloat16& l) {
  h = __float2bfloat16(x);
  l = __float2bfloat16(x - __bfloat162float(h));
}

__device__ __forceinline__ void split_pack2(float x, float y, uint32_t& h,
                                            uint32_t& l) {
  __nv_bfloat162 hb = __floats2bfloat162_rn(x, y);
  float xr = x - __bfloat162float(hb.x);
  float yr = y - __bfloat162float(hb.y);
  __nv_bfloat162 lb = __floats2bfloat162_rn(xr, yr);
  h = *reinterpret_cast<uint32_t*>(&hb);
  l = *reinterpret_cast<uint32_t*>(&lb);
}

// ---------------------------------------------------------------------------
// Preprocessing kernels
// ---------------------------------------------------------------------------
__global__ void split_kernel(const float* __restrict__ in,
                             __nv_bfloat16* __restrict__ hi,
                             __nv_bfloat16* __restrict__ lo, int n4) {
  int i = blockIdx.x * blockDim.x + threadIdx.x;
  if (i >= n4) return;
  float4 v = ((const float4*)in)[i];
  __nv_bfloat16 h0, l0, h1, l1, h2, l2, h3, l3;
  split2(v.x, h0, l0); split2(v.y, h1, l1);
  split2(v.z, h2, l2); split2(v.w, h3, l3);
  __nv_bfloat162* hp = (__nv_bfloat162*)hi;
  __nv_bfloat162* lp = (__nv_bfloat162*)lo;
  hp[i * 2 + 0] = __halves2bfloat162(h0, h1);
  hp[i * 2 + 1] = __halves2bfloat162(h2, h3);
  lp[i * 2 + 0] = __halves2bfloat162(l0, l1);
  lp[i * 2 + 1] = __halves2bfloat162(l2, l3);
}

__global__ void transpose_split_kernel(const float* __restrict__ W,
                                       __nv_bfloat16* __restrict__ Thi,
                                       __nv_bfloat16* __restrict__ Tlo,
                                       int N, int K) {
  __shared__ float t[32][33];
  int n0 = blockIdx.x * 32, k0 = blockIdx.y * 32;
  int tx = threadIdx.x, ty = threadIdx.y;
#pragma unroll
  for (int i = 0; i < 4; i++)
    t[ty + i * 8][tx] = W[(size_t)(k0 + ty + i * 8) * N + n0 + tx];
  __syncthreads();
#pragma unroll
  for (int i = 0; i < 4; i++) {
    int n = ty + i * 8;
    float x = t[tx][n];
    __nv_bfloat16 h, l;
    split2(x, h, l);
    size_t o = (size_t)(n0 + n) * K + k0 + tx;
    Thi[o] = h;
    Tlo[o] = l;
  }
}

// Transpose Wo[K][N] fp32 -> T[N][K] fp16 (single precision level)
__global__ void transpose_half_kernel(const float* __restrict__ W,
                                      __half* __restrict__ T, int N, int K) {
  __shared__ float t[32][33];
  int n0 = blockIdx.x * 32, k0 = blockIdx.y * 32;
  int tx = threadIdx.x, ty = threadIdx.y;
#pragma unroll
  for (int i = 0; i < 4; i++)
    t[ty + i * 8][tx] = W[(size_t)(k0 + ty + i * 8) * N + n0 + tx];
  __syncthreads();
#pragma unroll
  for (int i = 0; i < 4; i++) {
    int n = ty + i * 8;
    T[(size_t)(n0 + n) * K + k0 + tx] = __float2half(t[tx][n]);
  }
}

// ---------------------------------------------------------------------------
// bf16x3-split GEMM (QKV projection). 2 CTAs/SM.
// ---------------------------------------------------------------------------
#define GBM 128
#define GBN 128
#define GKC 32
#define RS 40
#define TILE_B (128 * RS * 2)
#define STAGE_B (4 * TILE_B)
#define GEMM_SMEM (2 * STAGE_B)

__global__ __launch_bounds__(256, 2) void gemm_bf16x3_kernel(
    const __nv_bfloat16* __restrict__ Ahi, const __nv_bfloat16* __restrict__ Alo,
    const __nv_bfloat16* __restrict__ Bhi, const __nv_bfloat16* __restrict__ Blo,
    float* __restrict__ C, int M, int N, int K) {
  extern __shared__ char smem[];
  const uint32_t sbase = smem_u32(smem);
  const int tid = threadIdx.x;
  const int wid = tid >> 5;
  const int lane = tid & 31;
  const int m0 = blockIdx.y * GBM;
  const int n0 = blockIdx.x * GBN;
  const int NC = K / GKC;

  const int wm = (wid & 3) * 32;
  const int wn = (wid >> 2) * 64;
  const int lrow = lane & 7;
  const int ltile = lane >> 3;
  const int a_r = (ltile & 1) * 8 + lrow;
  const int a_c = (ltile >> 1) * 8;
  const int b_r = (ltile >> 1) * 8 + lrow;
  const int b_c = (ltile & 1) * 8;

  const __nv_bfloat16* gA[2] = {Ahi + (size_t)m0 * K, Alo + (size_t)m0 * K};
  const __nv_bfloat16* gB[2] = {Bhi + (size_t)n0 * K, Blo + (size_t)n0 * K};

  auto load_stage = [&](int stg, int chunk) {
    const int kc = chunk * GKC;
    uint32_t sb = sbase + stg * STAGE_B;
#pragma unroll
    for (int t = 0; t < 4; t++) {
      const __nv_bfloat16* gp = (t < 2) ? gA[t] : gB[t - 2];
#pragma unroll
      for (int i = 0; i < 2; i++) {
        int v = tid + i * 256;
        int r = v >> 2;
        int c = (v & 3) * 8;
        cp_async16(sb + t * TILE_B + (uint32_t)(r * RS + c) * 2,
                   gp + (size_t)r * K + kc + c);
      }
    }
    CP_COMMIT();
  };

  float acc[2][8][4];
#pragma unroll
  for (int f = 0; f < 2; f++)
#pragma unroll
    for (int g = 0; g < 8; g++)
#pragma unroll
      for (int x = 0; x < 4; x++) acc[f][g][x] = 0.0f;

  load_stage(0, 0);

  for (int c = 0; c < NC; c++) {
    CP_WAIT0();
    __syncthreads();
    if (c + 1 < NC) load_stage((c + 1) & 1, c + 1);

    uint32_t sb = sbase + (c & 1) * STAGE_B;
#pragma unroll
    for (int kk = 0; kk < 2; kk++) {
      const int k0 = kk * 16;
      uint32_t ah[2][4], al[2][4], bh[8][2], bl[8][2];
#pragma unroll
      for (int f = 0; f < 2; f++) {
        uint32_t ar = (uint32_t)((wm + f * 16 + a_r) * RS + k0 + a_c) * 2;
        ldsm_x4(ah[f], sb + 0 * TILE_B + ar);
        ldsm_x4(al[f], sb + 1 * TILE_B + ar);
      }
#pragma unroll
      for (int g2 = 0; g2 < 4; g2++) {
        uint32_t br = (uint32_t)((wn + g2 * 16 + b_r) * RS + k0 + b_c) * 2;
        uint32_t rh[4], rl[4];
        ldsm_x4(rh, sb + 2 * TILE_B + br);
        ldsm_x4(rl, sb + 3 * TILE_B + br);
        bh[g2 * 2][0] = rh[0]; bh[g2 * 2][1] = rh[1];
        bh[g2 * 2 + 1][0] = rh[2]; bh[g2 * 2 + 1][1] = rh[3];
        bl[g2 * 2][0] = rl[0]; bl[g2 * 2][1] = rl[1];
        bl[g2 * 2 + 1][0] = rl[2]; bl[g2 * 2 + 1][1] = rl[3];
      }
#pragma unroll
      for (int f = 0; f < 2; f++)
#pragma unroll
        for (int g = 0; g < 8; g++) {
          mma16816(acc[f][g], ah[f], bh[g]);
          mma16816(acc[f][g], ah[f], bl[g]);
          mma16816(acc[f][g], al[f], bh[g]);
        }
    }
    __syncthreads();
  }

  const int gid = lane >> 2, tig = lane & 3;
#pragma unroll
  for (int f = 0; f < 2; f++) {
#pragma unroll
    for (int g = 0; g < 8; g++) {
      int row = m0 + wm + f * 16 + gid;
      int col = n0 + wn + g * 8 + tig * 2;
      *(float2*)(C + (size_t)row * N + col) = make_float2(acc[f][g][0], acc[f][g][1]);
      *(float2*)(C + (size_t)(row + 8) * N + col) = make_float2(acc[f][g][2], acc[f][g][3]);
    }
  }
}

// ---------------------------------------------------------------------------
// fp16 single-product GEMM (Wo projection: linear path, no softmax amplify).
// A half [M][K], B half [N][K]. Block 128x128x32, 2 buffers, high occupancy.
// ---------------------------------------------------------------------------
#define FTILE_B (128 * RS * 2)      // 10240 B per tile
#define FSTAGE_B (2 * FTILE_B)      // A, B
#define GEMM16_SMEM (2 * FSTAGE_B)  // 40960 B

__global__ __launch_bounds__(256, 2) void gemm_fp16_kernel(
    const __half* __restrict__ A, const __half* __restrict__ B,
    float* __restrict__ C, int M, int N, int K) {
  extern __shared__ char smem[];
  const uint32_t sbase = smem_u32(smem);
  const int tid = threadIdx.x;
  const int wid = tid >> 5;
  const int lane = tid & 31;
  const int m0 = blockIdx.y * GBM;
  const int n0 = blockIdx.x * GBN;
  const int NC = K / GKC;

  const int wm = (wid & 3) * 32;
  const int wn = (wid >> 2) * 64;
  const int lrow = lane & 7;
  const int ltile = lane >> 3;
  const int a_r = (ltile & 1) * 8 + lrow;
  const int a_c = (ltile >> 1) * 8;
  const int b_r = (ltile >> 1) * 8 + lrow;
  const int b_c = (ltile & 1) * 8;

  const __half* gA = A + (size_t)m0 * K;
  const __half* gB = B + (size_t)n0 * K;

  auto load_stage = [&](int stg, int chunk) {
    const int kc = chunk * GKC;
    uint32_t sb = sbase + stg * FSTAGE_B;
#pragma unroll
    for (int i = 0; i < 2; i++) {
      int v = tid + i * 256;
      int r = v >> 2;
      int c = (v & 3) * 8;
      cp_async16(sb + (uint32_t)(r * RS + c) * 2, gA + (size_t)r * K + kc + c);
      cp_async16(sb + FTILE_B + (uint32_t)(r * RS + c) * 2,
                 gB + (size_t)r * K + kc + c);
    }
    CP_COMMIT();
  };

  float acc[2][8][4];
#pragma unroll
  for (int f = 0; f < 2; f++)
#pragma unroll
    for (int g = 0; g < 8; g++)
#pragma unroll
      for (int x = 0; x < 4; x++) acc[f][g][x] = 0.0f;

  load_stage(0, 0);

  for (int c = 0; c < NC; c++) {
    CP_WAIT0();
    __syncthreads();
    if (c + 1 < NC) load_stage((c + 1) & 1, c + 1);

    uint32_t sb = sbase + (c & 1) * FSTAGE_B;
#pragma unroll
    for (int kk = 0; kk < 2; kk++) {
      const int k0 = kk * 16;
      uint32_t af[2][4], bf[8][2];
#pragma unroll
      for (int f = 0; f < 2; f++) {
        uint32_t ar = (uint32_t)((wm + f * 16 + a_r) * RS + k0 + a_c) * 2;
        ldsm_x4(af[f], sb + ar);
      }
#pragma unroll
      for (int g2 = 0; g2 < 4; g2++) {
        uint32_t br = (uint32_t)((wn + g2 * 16 + b_r) * RS + k0 + b_c) * 2;
        uint32_t r4[4];
        ldsm_x4(r4, sb + FTILE_B + br);
        bf[g2 * 2][0] = r4[0]; bf[g2 * 2][1] = r4[1];
        bf[g2 * 2 + 1][0] = r4[2]; bf[g2 * 2 + 1][1] = r4[3];
      }
#pragma unroll
      for (int f = 0; f < 2; f++)
#pragma unroll
        for (int g = 0; g < 8; g++) mma16816h(acc[f][g], af[f], bf[g]);
    }
    __syncthreads();
  }

  const int gid = lane >> 2, tig = lane & 3;
#pragma unroll
  for (int f = 0; f < 2; f++) {
#pragma unroll
    for (int g = 0; g < 8; g++) {
      int row = m0 + wm + f * 16 + gid;
      int col = n0 + wn + g * 8 + tig * 2;
      *(float2*)(C + (size_t)row * N + col) = make_float2(acc[f][g][0], acc[f][g][1]);
      *(float2*)(C + (size_t)(row + 8) * N + col) = make_float2(acc[f][g][2], acc[f][g][3]);
    }
  }
}

// ---------------------------------------------------------------------------
// RoPE + split: g_QKV fp32 -> Q/K (roped) and V, bf16 hi/lo, compact rows
// ---------------------------------------------------------------------------
__global__ void rope_split_kernel(const float* __restrict__ QKV) {
  const int QP = S * H * HD / 2;
  const int KP = S * KVH * HD / 2;
  int idx = blockIdx.x * blockDim.x + threadIdx.x;
  if (idx >= QP + 2 * KP) return;

  float xr, xi;
  __nv_bfloat162* hi_dst;
  __nv_bfloat162* lo_dst;

  if (idx < QP) {
    int i = idx & 31;
    int tmp = idx >> 5;
    int hh = tmp % H;
    int s = tmp / H;
    const float* p = QKV + (size_t)s * QKV_N + hh * HD + 2 * i;
    float a = p[0], b = p[1];
    float inv = 1.0f / powf(10000.0f, (2.0f * i) / (float)HD);
    float ang = (float)s * inv;
    float c = cosf(ang), sn = sinf(ang);
    xr = a * c - b * sn;
    xi = a * sn + b * c;
    size_t o = ((size_t)s * (H * HD) + hh * HD + 2 * i) / 2;
    hi_dst = (__nv_bfloat162*)g_Qhi + o;
    lo_dst = (__nv_bfloat162*)g_Qlo + o;
  } else if (idx < QP + KP) {
    int j = idx - QP;
    int i = j & 31;
    int tmp = j >> 5;
    int hh = tmp % KVH;
    int s = tmp / KVH;
    const float* p = QKV + (size_t)s * QKV_N + KCOL + hh * HD + 2 * i;
    float a = p[0], b = p[1];
    float inv = 1.0f / powf(10000.0f, (2.0f * i) / (float)HD);
    float ang = (float)s * inv;
    float c = cosf(ang), sn = sinf(ang);
    xr = a * c - b * sn;
    xi = a * sn + b * c;
    size_t o = ((size_t)s * (KVH * HD) + hh * HD + 2 * i) / 2;
    hi_dst = (__nv_bfloat162*)g_Khi + o;
    lo_dst = (__nv_bfloat162*)g_Klo + o;
  } else {
    int j = idx - QP - KP;
    int i = j & 31;
    int tmp = j >> 5;
    int hh = tmp % KVH;
    int s = tmp / KVH;
    const float* p = QKV + (size_t)s * QKV_N + VCOL + hh * HD + 2 * i;
    xr = p[0];
    xi = p[1];
    size_t o = ((size_t)s * (KVH * HD) + hh * HD + 2 * i) / 2;
    hi_dst = (__nv_bfloat162*)g_Vhi + o;
    lo_dst = (__nv_bfloat162*)g_Vlo + o;
  }

  __nv_bfloat16 h0, l0, h1, l1;
  split2(xr, h0, l0);
  split2(xi, h1, l1);
  *hi_dst = __halves2bfloat162(h0, h1);
  *lo_dst = __halves2bfloat162(l0, l1);
}

// ---------------------------------------------------------------------------
// Tensor-core flash attention. O written as fp16 (feeds fp16 Wo GEMM).
// ---------------------------------------------------------------------------
#define ABQ 128
#define ABKV 64
#define ARS 72
#define Q_ELEMS (ABQ * ARS)
#define KV_TILE (ABKV * ARS)
#define KV_STAGE (4 * KV_TILE)
#define ATT_SMEM ((2 * Q_ELEMS + 2 * KV_STAGE) * 2)

__global__ __launch_bounds__(256) void attn_mma_kernel(
    const __nv_bfloat16* __restrict__ Qhi, const __nv_bfloat16* __restrict__ Qlo,
    const __nv_bfloat16* __restrict__ Khi, const __nv_bfloat16* __restrict__ Klo,
    const __nv_bfloat16* __restrict__ Vhi, const __nv_bfloat16* __restrict__ Vlo,
    __half* __restrict__ O16) {
  extern __shared__ char sbuf[];
  const uint32_t sbase = smem_u32(sbuf);
  const int tid = threadIdx.x;
  const int wid = tid >> 5;
  const int lane = tid & 31;
  const int h = blockIdx.x;
  const int kvh = h / NREP;
  const int q0 = ((int)gridDim.y - 1 - (int)blockIdx.y) * ABQ;
  const int wm = wid * 16;

  const int lrow = lane & 7;
  const int ltile = lane >> 3;
  const int a_r = (ltile & 1) * 8 + lrow;
  const int a_c = (ltile >> 1) * 8;
  const int b_r = (ltile >> 1) * 8 + lrow;
  const int b_c = (ltile & 1) * 8;
  const int gid = lane >> 2, tig = lane & 3;

  const uint32_t qhi_s = sbase;
  const uint32_t qlo_s = sbase + Q_ELEMS * 2;

#pragma unroll
  for (int i = 0; i < 4; i++) {
    int v = tid + i * 256;
    int r = v >> 3, c = v & 7;
    size_t g = (size_t)(q0 + r) * (H * HD) + h * HD + c * 8;
    uint32_t so = (uint32_t)(r * ARS + c * 8) * 2;
    cp_async16(qhi_s + so, Qhi + g);
    cp_async16(qlo_s + so, Qlo + g);
  }

  auto load_kv = [&](int stg, int kv0) {
    uint32_t base = sbase + (2 * Q_ELEMS + stg * KV_STAGE) * 2;
#pragma unroll
    for (int i = 0; i < 2; i++) {
      int v = tid + i * 256;
      int r = v >> 3, c = v & 7;
      size_t g = (size_t)(kv0 + r) * (KVH * HD) + kvh * HD + c * 8;
      uint32_t so = (uint32_t)(r * ARS + c * 8) * 2;
      cp_async16(base + 0 * KV_TILE * 2 + so, Khi + g);
      cp_async16(base + 1 * KV_TILE * 2 + so, Klo + g);
      cp_async16(base + 2 * KV_TILE * 2 + so, Vhi + g);
      cp_async16(base + 3 * KV_TILE * 2 + so, Vlo + g);
    }
    CP_COMMIT();
  };

  load_kv(0, 0);

  const int ntiles = (q0 + ABQ) / ABKV;
  float m_[2] = {-1e30f, -1e30f};
  float l_[2] = {0.0f, 0.0f};
  float o[8][4];
#pragma unroll
  for (int nf = 0; nf < 8; nf++)
#pragma unroll
    for (int j = 0; j < 4; j++) o[nf][j] = 0.0f;

  const float SCL = 0.18033688011112042f;
  const int row0 = q0 + wm + gid;

  for (int t = 0; t < ntiles; t++) {
    const int kv0 = t * ABKV;
    CP_WAIT0();
    __syncthreads();
    if (t + 1 < ntiles) load_kv((t + 1) & 1, kv0 + ABKV);

    const uint32_t kvb = sbase + (2 * Q_ELEMS + (t & 1) * KV_STAGE) * 2;

    float sc[8][4];
#pragma unroll
    for (int nf = 0; nf < 8; nf++)
#pragma unroll
      for (int j = 0; j < 4; j++) sc[nf][j] = 0.0f;

#pragma unroll
    for (int ks = 0; ks < 4; ks++) {
      const int k0 = ks * 16;
      uint32_t ah[4], al[4];
      uint32_t ar = (uint32_t)((wm + a_r) * ARS + k0 + a_c) * 2;
      ldsm_x4(ah, qhi_s + ar);
      ldsm_x4(al, qlo_s + ar);
#pragma unroll
      for (int ng = 0; ng < 4; ng++) {
        uint32_t br = kvb + (uint32_t)((ng * 16 + b_r) * ARS + k0 + b_c) * 2;
        uint32_t rh[4], rl[4];
        ldsm_x4(rh, br);
        ldsm_x4(rl, br + KV_TILE * 2);
        mma16816(sc[ng * 2], ah, rh);
        mma16816(sc[ng * 2], ah, rl);
        mma16816(sc[ng * 2], al, rh);
        mma16816(sc[ng * 2 + 1], ah, rh + 2);
        mma16816(sc[ng * 2 + 1], ah, rl + 2);
        mma16816(sc[ng * 2 + 1], al, rh + 2);
      }
    }

    const bool nomask = (kv0 + ABKV - 1 <= q0 + wm);
    if (nomask) {
#pragma unroll
      for (int nf = 0; nf < 8; nf++)
#pragma unroll
        for (int j = 0; j < 4; j++) sc[nf][j] *= SCL;
    } else {
#pragma unroll
      for (int nf = 0; nf < 8; nf++) {
        int col = kv0 + nf * 8 + tig * 2;
#pragma unroll
        for (int j = 0; j < 4; j++) {
          int cc = col + (j & 1);
          int rr = row0 + ((j >> 1) << 3);
          sc[nf][j] = (cc <= rr) ? sc[nf][j] * SCL : -1e30f;
        }
      }
    }

    float mx0 = -1e30f, mx1 = -1e30f;
#pragma unroll
    for (int nf = 0; nf < 8; nf++) {
      mx0 = fmaxf(mx0, fmaxf(sc[nf][0], sc[nf][1]));
      mx1 = fmaxf(mx1, fmaxf(sc[nf][2], sc[nf][3]));
    }
    mx0 = fmaxf(mx0, __shfl_xor_sync(0xffffffffu, mx0, 1));
    mx0 = fmaxf(mx0, __shfl_xor_sync(0xffffffffu, mx0, 2));
    mx1 = fmaxf(mx1, __shfl_xor_sync(0xffffffffu, mx1, 1));
    mx1 = fmaxf(mx1, __shfl_xor_sync(0xffffffffu, mx1, 2));
    float mn0 = fmaxf(m_[0], mx0);
    float mn1 = fmaxf(m_[1], mx1);
    float c0 = exp2_poly(m_[0] - mn0);
    float c1 = exp2_poly(m_[1] - mn1);
    m_[0] = mn0;
    m_[1] = mn1;

    float s0 = 0.0f, s1 = 0.0f;
#pragma unroll
    for (int nf = 0; nf < 8; nf++) {
      float p0 = exp2_poly(sc[nf][0] - mn0);
      float p1 = exp2_poly(sc[nf][1] - mn0);
      float p2 = exp2_poly(sc[nf][2] - mn1);
      float p3 = exp2_poly(sc[nf][3] - mn1);
      sc[nf][0] = p0; sc[nf][1] = p1; sc[nf][2] = p2; sc[nf][3] = p3;
      s0 += p0 + p1;
      s1 += p2 + p3;
    }
    l_[0] = l_[0] * c0 + s0;
    l_[1] = l_[1] * c1 + s1;
#pragma unroll
    for (int nf = 0; nf < 8; nf++) {
      o[nf][0] *= c0; o[nf][1] *= c0;
      o[nf][2] *= c1; o[nf][3] *= c1;
    }

    const uint32_t vhb = kvb + 2 * KV_TILE * 2;
#pragma unroll
    for (int ks = 0; ks < 4; ks++) {
      uint32_t phi[4], plo[4];
      split_pack2(sc[2 * ks][0], sc[2 * ks][1], phi[0], plo[0]);
      split_pack2(sc[2 * ks][2], sc[2 * ks][3], phi[1], plo[1]);
      split_pack2(sc[2 * ks + 1][0], sc[2 * ks + 1][1], phi[2], plo[2]);
      split_pack2(sc[2 * ks + 1][2], sc[2 * ks + 1][3], phi[3], plo[3]);
#pragma unroll
      for (int dg = 0; dg < 4; dg++) {
        uint32_t va = vhb + (uint32_t)((ks * 16 + a_r) * ARS + dg * 16 + a_c) * 2;
        uint32_t vh[4], vl[4];
        ldsm_x4_trans(vh, va);
        ldsm_x4_trans(vl, va + KV_TILE * 2);
        mma16816(o[dg * 2], phi, vh);
        mma16816(o[dg * 2], phi, vl);
        mma16816(o[dg * 2], plo, vh);
        mma16816(o[dg * 2 + 1], phi, vh + 2);
        mma16816(o[dg * 2 + 1], phi, vl + 2);
        mma16816(o[dg * 2 + 1], plo, vh + 2);
      }
    }
  }

  l_[0] += __shfl_xor_sync(0xffffffffu, l_[0], 1);
  l_[0] += __shfl_xor_sync(0xffffffffu, l_[0], 2);
  l_[1] += __shfl_xor_sync(0xffffffffu, l_[1], 1);
  l_[1] += __shfl_xor_sync(0xffffffffu, l_[1], 2);
  float inv0 = 1.0f / l_[0];
  float inv1 = 1.0f / l_[1];

#pragma unroll
  for (int nf = 0; nf < 8; nf++) {
    int col = h * HD + nf * 8 + tig * 2;
    *(__half2*)(O16 + (size_t)row0 * (H * HD) + col) =
        __floats2half2_rn(o[nf][0] * inv0, o[nf][1] * inv0);
    *(__half2*)(O16 + (size_t)(row0 + 8) * (H * HD) + col) =
        __floats2half2_rn(o[nf][2] * inv1, o[nf][3] * inv1);
  }
}

// ---------------------------------------------------------------------------
// Launch
// ---------------------------------------------------------------------------
extern "C" void kernel_launch(void* const* d_in, const int* in_sizes, int n_in,
                              void* d_out, int out_size) {
  const float* hs = (const float*)d_in[0];
  const float* Wq = (const float*)d_in[1];
  const float* Wk = (const float*)d_in[2];
  const float* Wv = (const float*)d_in[3];
  const float* Wo = (const float*)d_in[4];
  float* out = (float*)d_out;

  float* QKVp;
  __nv_bfloat16 *Xhi, *Xlo, *WqkvThi, *WqkvTlo;
  __nv_bfloat16 *Qhi, *Qlo, *Khi, *Klo, *Vhi, *Vlo;
  __half *O16, *WoT16;
  cudaGetSymbolAddress((void**)&QKVp, g_QKV);
  cudaGetSymbolAddress((void**)&Xhi, g_Xhi);
  cudaGetSymbolAddress((void**)&Xlo, g_Xlo);
  cudaGetSymbolAddress((void**)&WqkvThi, g_WqkvThi);
  cudaGetSymbolAddress((void**)&WqkvTlo, g_WqkvTlo);
  cudaGetSymbolAddress((void**)&Qhi, g_Qhi);
  cudaGetSymbolAddress((void**)&Qlo, g_Qlo);
  cudaGetSymbolAddress((void**)&Khi, g_Khi);
  cudaGetSymbolAddress((void**)&Klo, g_Klo);
  cudaGetSymbolAddress((void**)&Vhi, g_Vhi);
  cudaGetSymbolAddress((void**)&Vlo, g_Vlo);
  cudaGetSymbolAddress((void**)&O16, g_O16);
  cudaGetSymbolAddress((void**)&WoT16, g_WoT16);

  // 1. split activations
  {
    int n4 = S * D / 4;
    split_kernel<<<(n4 + 255) / 256, 256>>>(hs, Xhi, Xlo, n4);
  }

  // 2. transpose weights: Wq/Wk/Wv -> bf16 hi/lo fused, Wo -> fp16
  {
    dim3 blk(32, 8);
    transpose_split_kernel<<<dim3(D / 32, D / 32), blk>>>(Wq, WqkvThi, WqkvTlo, D, D);
    transpose_split_kernel<<<dim3(512 / 32, D / 32), blk>>>(
        Wk, WqkvThi + (size_t)KCOL * D, WqkvTlo + (size_t)KCOL * D, 512, D);
    transpose_split_kernel<<<dim3(512 / 32, D / 32), blk>>>(
        Wv, WqkvThi + (size_t)VCOL * D, WqkvTlo + (size_t)VCOL * D, 512, D);
    transpose_half_kernel<<<dim3(D / 32, D / 32), blk>>>(Wo, WoT16, D, D);
  }

  cudaFuncSetAttribute(gemm_bf16x3_kernel,
                       cudaFuncAttributeMaxDynamicSharedMemorySize, GEMM_SMEM);
  cudaFuncSetAttribute(gemm_fp16_kernel,
                       cudaFuncAttributeMaxDynamicSharedMemorySize, GEMM16_SMEM);

  // 3. fused QKV projection (bf16x3)
  {
    dim3 grid(QKV_N / GBN, S / GBM);
    gemm_bf16x3_kernel<<<grid, 256, GEMM_SMEM>>>(Xhi, Xlo, WqkvThi, WqkvTlo,
                                                 QKVp, S, QKV_N, D);
  }

  // 4. RoPE + split Q/K/V
  {
    int total = S * H * HD / 2 + 2 * (S * KVH * HD / 2);
    rope_split_kernel<<<(total + 255) / 256, 256>>>(QKVp);
  }

  // 5. tensor-core flash attention -> fp16 O
  {
    cudaFuncSetAttribute(attn_mma_kernel,
                         cudaFuncAttributeMaxDynamicSharedMemorySize, ATT_SMEM);
    dim3 grid(H, S / ABQ);
    attn_mma_kernel<<<grid, 256, ATT_SMEM>>>(Qhi, Qlo, Khi, Klo, Vhi, Vlo, O16);
  }

  // 6. output projection (fp16 single-product, linear path)
  {
    dim3 grid(D / GBN, S / GBM);
    gemm_fp16_kernel<<<grid, 256, GEMM16_SMEM>>>(O16, WoT16, out, S, D, D);
  }
}